// round 16
// baseline (speedup 1.0000x reference)
#include <cuda_runtime.h>

// ----------------------------------------------------------------------------
// GCN 5-layer inference, N=50000 nodes, E=800000 edges, 128->64->64->64->64->16
//
// Output layout (flattened tuple): [log_softmax N*16][e1 N*64][e2][e3][e4][e5 N*16]
//
// This round (vs 192.1us R15):
//   - Software-pipelined layer boundaries: agg_i and gemm_{i+1} split into
//     row halves A/B; gemm_{i+1}(A) runs CONCURRENT with agg_i(B)
//     (agg = L2-bound, gemm = FMA-bound -> real overlap). Ping-pong g_xw
//     buffers remove the WAR hazard.
//   - CSR build still on its own stream under gemm1; agg16+lsm fused.
// ----------------------------------------------------------------------------

constexpr int N_NODES = 50000;
constexpr int N_EDGES = 800000;
constexpr int SCAN_CHUNK = 1024;
constexpr int NB = (N_NODES + SCAN_CHUNK - 1) / SCAN_CHUNK;   // 49

constexpr int ROWS_A = 25024;                 // 391 * 64
constexpr int ROWS_B = N_NODES - ROWS_A;      // 24976
constexpr int GEMM_BLK_A = ROWS_A / 64;       // 391
constexpr int GEMM_BLK_B = (ROWS_B + 63) / 64;// 391 (last partial)

// Ping-pong scratch for per-layer dense GEMM results (N x 64 fp32 each).
__device__ float g_xw0[(size_t)N_NODES * 64];
__device__ float g_xw1[(size_t)N_NODES * 64];

// CSR scratch
__device__ int   g_deg[N_NODES];
__device__ int   g_off[N_NODES + 1];
__device__ int   g_bsum[NB];
__device__ int   g_ecol[N_EDGES];
__device__ float g_ew[N_EDGES];

// ----------------------------------------------------------------------------
// Dense GEMM: XW[rows] = act(X)[rows x K] @ W[K x COLS], rows from row_base.
// 64-row tile per block; thread tile 4x4; K chunked by 64. (Proven kernel.)
// ----------------------------------------------------------------------------
template <int K, int COLS, bool RELU>
__global__ void gemm_kernel(const float* __restrict__ X, const float* __restrict__ W,
                            float* __restrict__ XW, int row_base) {
    constexpr int TX = COLS / 4;
    constexpr int NT = TX * 16;

    __shared__ float sx[64][68];
    __shared__ float sw[64][COLS];

    const int tid  = threadIdx.x;
    const int tx   = tid % TX;
    const int ty   = tid / TX;
    const int row0 = row_base + blockIdx.x * 64;

    float4 acc[4];
#pragma unroll
    for (int r = 0; r < 4; r++) acc[r] = make_float4(0.f, 0.f, 0.f, 0.f);

    for (int kt = 0; kt < K; kt += 64) {
        if (kt) __syncthreads();

        for (int i = tid; i < 64 * 16; i += NT) {
            int r = i >> 4, q = i & 15;
            int gr = row0 + r;
            float4 v = make_float4(0.f, 0.f, 0.f, 0.f);
            if (gr < N_NODES)
                v = *(const float4*)(X + (size_t)gr * K + kt + q * 4);
            if (RELU) {
                v.x = fmaxf(v.x, 0.f); v.y = fmaxf(v.y, 0.f);
                v.z = fmaxf(v.z, 0.f); v.w = fmaxf(v.w, 0.f);
            }
            *(float4*)&sx[r][q * 4] = v;
        }
        for (int i = tid; i < 64 * (COLS / 4); i += NT) {
            int k = i / (COLS / 4), q = i % (COLS / 4);
            *(float4*)&sw[k][q * 4] = *(const float4*)(W + (size_t)(kt + k) * COLS + q * 4);
        }
        __syncthreads();

#pragma unroll
        for (int k = 0; k < 64; k += 4) {
            float4 b0 = *(const float4*)&sw[k + 0][tx * 4];
            float4 b1 = *(const float4*)&sw[k + 1][tx * 4];
            float4 b2 = *(const float4*)&sw[k + 2][tx * 4];
            float4 b3 = *(const float4*)&sw[k + 3][tx * 4];
#pragma unroll
            for (int r = 0; r < 4; r++) {
                float4 a = *(const float4*)&sx[ty * 4 + r][k];
                acc[r].x += a.x * b0.x; acc[r].y += a.x * b0.y;
                acc[r].z += a.x * b0.z; acc[r].w += a.x * b0.w;
                acc[r].x += a.y * b1.x; acc[r].y += a.y * b1.y;
                acc[r].z += a.y * b1.z; acc[r].w += a.y * b1.w;
                acc[r].x += a.z * b2.x; acc[r].y += a.z * b2.y;
                acc[r].z += a.z * b2.z; acc[r].w += a.z * b2.w;
                acc[r].x += a.w * b3.x; acc[r].y += a.w * b3.y;
                acc[r].z += a.w * b3.z; acc[r].w += a.w * b3.w;
            }
        }
    }

#pragma unroll
    for (int r = 0; r < 4; r++) {
        int gr = row0 + ty * 4 + r;
        if (gr < N_NODES)
            *(float4*)(XW + (size_t)gr * COLS + tx * 4) = acc[r];
    }
}

// ----------------------------------------------------------------------------
// CSR build (proven)
// ----------------------------------------------------------------------------
__global__ void zero_deg_kernel() {
    int i = blockIdx.x * blockDim.x + threadIdx.x;
    if (i < N_NODES) g_deg[i] = 0;
}

__global__ void hist_kernel(const int* __restrict__ erow) {
    int e = blockIdx.x * blockDim.x + threadIdx.x;
    if (e < N_EDGES) atomicAdd(&g_deg[__ldg(erow + e)], 1);
}

__global__ void scan1_kernel() {
    __shared__ int sh[256];
    int b = blockIdx.x, t = threadIdx.x;
    int base = b * SCAN_CHUNK + t * 4;
    int d0 = 0, d1 = 0, d2 = 0, d3 = 0;
    if (base + 0 < N_NODES) d0 = g_deg[base + 0];
    if (base + 1 < N_NODES) d1 = g_deg[base + 1];
    if (base + 2 < N_NODES) d2 = g_deg[base + 2];
    if (base + 3 < N_NODES) d3 = g_deg[base + 3];
    int s = d0 + d1 + d2 + d3;
    sh[t] = s;
    __syncthreads();
    for (int off = 1; off < 256; off <<= 1) {
        int v = (t >= off) ? sh[t - off] : 0;
        __syncthreads();
        sh[t] += v;
        __syncthreads();
    }
    int excl = sh[t] - s;
    if (t == 255) g_bsum[b] = sh[255];
    if (base + 0 < N_NODES) g_off[base + 0] = excl;
    if (base + 1 < N_NODES) g_off[base + 1] = excl + d0;
    if (base + 2 < N_NODES) g_off[base + 2] = excl + d0 + d1;
    if (base + 3 < N_NODES) g_off[base + 3] = excl + d0 + d1 + d2;
}

__global__ void scan2_kernel() {
    __shared__ int sh[64];
    int t = threadIdx.x;
    int v = (t < NB) ? g_bsum[t] : 0;
    sh[t] = v;
    __syncthreads();
    for (int off = 1; off < 64; off <<= 1) {
        int u = (t >= off) ? sh[t - off] : 0;
        __syncthreads();
        sh[t] += u;
        __syncthreads();
    }
    if (t < NB) g_bsum[t] = sh[t] - v;   // exclusive
}

__global__ void scan3_kernel() {
    int i = blockIdx.x * blockDim.x + threadIdx.x;
    if (i < N_NODES) {
        g_off[i] += g_bsum[i / SCAN_CHUNK];
        g_deg[i] = 0;
    }
    if (i == 0) g_off[N_NODES] = N_EDGES;
}

__global__ void fill_kernel(const int* __restrict__ erow, const int* __restrict__ ecol,
                            const float* __restrict__ ew) {
    int e = blockIdx.x * blockDim.x + threadIdx.x;
    if (e >= N_EDGES) return;
    int r = __ldg(erow + e);
    int pos = g_off[r] + atomicAdd(&g_deg[r], 1);
    g_ecol[pos] = __ldg(ecol + e);
    g_ew[pos]   = __ldg(ew + e);
}

// ----------------------------------------------------------------------------
// Per-row aggregation (64 features) over a row range.
// ----------------------------------------------------------------------------
__global__ void agg64_kernel(const float* __restrict__ bias, const float* __restrict__ XW,
                             float* __restrict__ dst, int row_base, int nrows) {
    int t = blockIdx.x * blockDim.x + threadIdx.x;
    if (t >= nrows * 16) return;
    int row = row_base + (t >> 4), q = t & 15;
    float4 acc = *(const float4*)(bias + q * 4);
    int i = __ldg(&g_off[row]), end = __ldg(&g_off[row + 1]);
    for (; i + 1 < end; i += 2) {
        int c0 = __ldg(&g_ecol[i]);     float w0 = __ldg(&g_ew[i]);
        int c1 = __ldg(&g_ecol[i + 1]); float w1 = __ldg(&g_ew[i + 1]);
        float4 v0 = *(const float4*)(XW + (size_t)c0 * 64 + q * 4);
        float4 v1 = *(const float4*)(XW + (size_t)c1 * 64 + q * 4);
        acc.x += w0 * v0.x + w1 * v1.x;
        acc.y += w0 * v0.y + w1 * v1.y;
        acc.z += w0 * v0.z + w1 * v1.z;
        acc.w += w0 * v0.w + w1 * v1.w;
    }
    if (i < end) {
        int c = __ldg(&g_ecol[i]); float w = __ldg(&g_ew[i]);
        float4 v = *(const float4*)(XW + (size_t)c * 64 + q * 4);
        acc.x += w * v.x; acc.y += w * v.y; acc.z += w * v.z; acc.w += w * v.w;
    }
    *(float4*)(dst + (size_t)row * 64 + q * 4) = acc;
}

// ----------------------------------------------------------------------------
// Layer-5 aggregation (16 features) + fused log_softmax, over a row range.
// ----------------------------------------------------------------------------
__global__ void agg16_lsm_kernel(const float* __restrict__ bias, const float* __restrict__ XW,
                                 float* __restrict__ e5, float* __restrict__ out,
                                 int row_base, int nrows) {
    int t = blockIdx.x * blockDim.x + threadIdx.x;
    bool valid = (t < nrows * 4);
    int tc = valid ? t : (nrows * 4 - 1);
    int row = row_base + (tc >> 2), q = tc & 3;

    float4 acc = *(const float4*)(bias + q * 4);
    int i = __ldg(&g_off[row]), end = __ldg(&g_off[row + 1]);
    for (; i + 1 < end; i += 2) {
        int c0 = __ldg(&g_ecol[i]);     float w0 = __ldg(&g_ew[i]);
        int c1 = __ldg(&g_ecol[i + 1]); float w1 = __ldg(&g_ew[i + 1]);
        float4 v0 = *(const float4*)(XW + (size_t)c0 * 16 + q * 4);
        float4 v1 = *(const float4*)(XW + (size_t)c1 * 16 + q * 4);
        acc.x += w0 * v0.x + w1 * v1.x;
        acc.y += w0 * v0.y + w1 * v1.y;
        acc.z += w0 * v0.z + w1 * v1.z;
        acc.w += w0 * v0.w + w1 * v1.w;
    }
    if (i < end) {
        int c = __ldg(&g_ecol[i]); float w = __ldg(&g_ew[i]);
        float4 v = *(const float4*)(XW + (size_t)c * 16 + q * 4);
        acc.x += w * v.x; acc.y += w * v.y; acc.z += w * v.z; acc.w += w * v.w;
    }
    if (valid)
        *(float4*)(e5 + (size_t)row * 16 + q * 4) = acc;

    float m = fmaxf(fmaxf(acc.x, acc.y), fmaxf(acc.z, acc.w));
    m = fmaxf(m, __shfl_xor_sync(0xffffffffu, m, 1));
    m = fmaxf(m, __shfl_xor_sync(0xffffffffu, m, 2));
    float s = expf(acc.x - m) + expf(acc.y - m) + expf(acc.z - m) + expf(acc.w - m);
    s += __shfl_xor_sync(0xffffffffu, s, 1);
    s += __shfl_xor_sync(0xffffffffu, s, 2);
    float lse = m + logf(s);
    if (valid) {
        float4 o;
        o.x = acc.x - lse; o.y = acc.y - lse; o.z = acc.z - lse; o.w = acc.w - lse;
        *(float4*)(out + (size_t)row * 16 + q * 4) = o;
    }
}

// ----------------------------------------------------------------------------
// Launch: pipelined A/B halves across two streams + CSR stream.
// ----------------------------------------------------------------------------
extern "C" void kernel_launch(void* const* d_in, const int* in_sizes, int n_in,
                              void* d_out, int out_size) {
    const float* x    = (const float*)d_in[0];
    const int*   erow = (const int*)d_in[1];
    const int*   ecol = (const int*)d_in[2];
    const float* ew   = (const float*)d_in[3];
    const float* W1 = (const float*)d_in[4];  const float* b1 = (const float*)d_in[5];
    const float* W2 = (const float*)d_in[6];  const float* b2 = (const float*)d_in[7];
    const float* W3 = (const float*)d_in[8];  const float* b3 = (const float*)d_in[9];
    const float* W4 = (const float*)d_in[10]; const float* b4 = (const float*)d_in[11];
    const float* W5 = (const float*)d_in[12]; const float* b5 = (const float*)d_in[13];

    float* out = (float*)d_out;
    float* e1 = out + (size_t)N_NODES * 16;
    float* e2 = e1 + (size_t)N_NODES * 64;
    float* e3 = e2 + (size_t)N_NODES * 64;
    float* e4 = e3 + (size_t)N_NODES * 64;
    float* e5 = e4 + (size_t)N_NODES * 64;

    static cudaStream_t s1 = nullptr, s2 = nullptr;
    static cudaEvent_t  ev[16];
    if (s1 == nullptr) {
        cudaStreamCreateWithFlags(&s1, cudaStreamNonBlocking);
        cudaStreamCreateWithFlags(&s2, cudaStreamNonBlocking);
        for (int i = 0; i < 16; i++) cudaEventCreateWithFlags(&ev[i], cudaEventDisableTiming);
    }

    // Resolve ping-pong buffer addresses (device-symbol addresses are fixed).
    static float *xw0 = nullptr, *xw1 = nullptr;
    if (xw0 == nullptr) {
        cudaGetSymbolAddress((void**)&xw0, g_xw0);
        cudaGetSymbolAddress((void**)&xw1, g_xw1);
    }

    const int NB_N   = (N_NODES + 255) / 256;
    const int NB_E   = (N_EDGES + 255) / 256;
    const int AGA64  = ROWS_A * 16 / 256;          // 1564
    const int AGB64  = ROWS_B * 16 / 256;          // 1561
    const int AGA16  = ROWS_A * 4 / 256;           // 391
    const int AGB16  = (ROWS_B * 4 + 255) / 256;   // 391 (guarded)

    // ---- fork ----
    cudaEventRecord(ev[0], 0);
    cudaStreamWaitEvent(s1, ev[0], 0);
    cudaStreamWaitEvent(s2, ev[0], 0);

    // CSR build on s2.
    zero_deg_kernel<<<NB_N, 256, 0, s2>>>();
    hist_kernel<<<NB_E, 256, 0, s2>>>(erow);
    scan1_kernel<<<NB, 256, 0, s2>>>();
    scan2_kernel<<<1, 64, 0, s2>>>();
    scan3_kernel<<<NB_N, 256, 0, s2>>>();
    fill_kernel<<<NB_E, 256, 0, s2>>>(erow, ecol, ew);
    cudaEventRecord(ev[1], s2);                    // CSR done

    // gemm1 halves on s0 / s1.
    gemm_kernel<128, 64, false><<<GEMM_BLK_A, 256>>>(x, W1, xw0, 0);
    gemm_kernel<128, 64, false><<<GEMM_BLK_B, 256, 0, s1>>>(x, W1, xw0, ROWS_A);
    cudaEventRecord(ev[2], s1);                    // gemm1(B) done

    // ---- pipelined layers ----
    // Boundary 1: agg1 / gemm2
    cudaStreamWaitEvent(0, ev[2], 0);
    cudaStreamWaitEvent(0, ev[1], 0);
    agg64_kernel<<<AGA64, 256>>>(b1, xw0, e1, 0, ROWS_A);
    cudaEventRecord(ev[3], 0);                     // agg1(A) done
    gemm_kernel<64, 64, true><<<GEMM_BLK_A, 256>>>(e1, W2, xw1, 0);
    cudaStreamWaitEvent(s1, ev[3], 0);
    agg64_kernel<<<AGB64, 256, 0, s1>>>(b1, xw0, e1, ROWS_A, ROWS_B);
    gemm_kernel<64, 64, true><<<GEMM_BLK_B, 256, 0, s1>>>(e1, W2, xw1, ROWS_A);
    cudaEventRecord(ev[4], s1);                    // gemm2(B) done

    // Boundary 2: agg2 / gemm3
    cudaStreamWaitEvent(0, ev[4], 0);
    agg64_kernel<<<AGA64, 256>>>(b2, xw1, e2, 0, ROWS_A);
    cudaEventRecord(ev[5], 0);
    gemm_kernel<64, 64, true><<<GEMM_BLK_A, 256>>>(e2, W3, xw0, 0);
    cudaStreamWaitEvent(s1, ev[5], 0);
    agg64_kernel<<<AGB64, 256, 0, s1>>>(b2, xw1, e2, ROWS_A, ROWS_B);
    gemm_kernel<64, 64, true><<<GEMM_BLK_B, 256, 0, s1>>>(e2, W3, xw0, ROWS_A);
    cudaEventRecord(ev[6], s1);

    // Boundary 3: agg3 / gemm4
    cudaStreamWaitEvent(0, ev[6], 0);
    agg64_kernel<<<AGA64, 256>>>(b3, xw0, e3, 0, ROWS_A);
    cudaEventRecord(ev[7], 0);
    gemm_kernel<64, 64, true><<<GEMM_BLK_A, 256>>>(e3, W4, xw1, 0);
    cudaStreamWaitEvent(s1, ev[7], 0);
    agg64_kernel<<<AGB64, 256, 0, s1>>>(b3, xw0, e3, ROWS_A, ROWS_B);
    gemm_kernel<64, 64, true><<<GEMM_BLK_B, 256, 0, s1>>>(e3, W4, xw1, ROWS_A);
    cudaEventRecord(ev[8], s1);

    // Boundary 4: agg4 / gemm5 (COLS=16, 64 threads)
    cudaStreamWaitEvent(0, ev[8], 0);
    agg64_kernel<<<AGA64, 256>>>(b4, xw1, e4, 0, ROWS_A);
    cudaEventRecord(ev[9], 0);
    gemm_kernel<64, 16, true><<<GEMM_BLK_A, 64>>>(e4, W5, xw0, 0);
    cudaStreamWaitEvent(s1, ev[9], 0);
    agg64_kernel<<<AGB64, 256, 0, s1>>>(b4, xw1, e4, ROWS_A, ROWS_B);
    gemm_kernel<64, 16, true><<<GEMM_BLK_B, 64, 0, s1>>>(e4, W5, xw0, ROWS_A);
    cudaEventRecord(ev[10], s1);

    // Final: agg16+lsm halves (need full gemm5), then join.
    cudaStreamWaitEvent(0, ev[10], 0);
    agg16_lsm_kernel<<<AGA16, 256>>>(b5, xw0, e5, out, 0, ROWS_A);
    cudaEventRecord(ev[11], 0);
    cudaStreamWaitEvent(s1, ev[11], 0);
    agg16_lsm_kernel<<<AGB16, 256, 0, s1>>>(b5, xw0, e5, out, ROWS_A, ROWS_B);
    cudaEventRecord(ev[12], s1);
    cudaStreamWaitEvent(0, ev[12], 0);             // join everything to s0
}